// round 1
// baseline (speedup 1.0000x reference)
#include <cuda_runtime.h>
#include <cuda_bf16.h>

// Problem constants (from reference: TRACK_SIZE=16, C=240 -> T=15 tracks).
#define TRACK_SZ   16
#define C_TOT      240
#define N_TRACKS   15
#define ROW_F4     60      // float4 elements per row (240 floats / 4)
#define U_J        16      // consecutive j-rows handled per thread

// min(lengths) computed on-device (lengths are device data; host never sees them).
__device__ int g_minlen;

__global__ void rc_min_kernel(const int* __restrict__ lengths, int B) {
    int m = 0x7fffffff;
    for (int i = 0; i < B; ++i) m = min(m, lengths[i]);
    g_minlen = m;
}

// Thread layout:
//   threadIdx.x = q in [0,60)   : float4 column within the row (stores coalesced)
//   threadIdx.y in [0,4)        : sub-group of j-chunks inside the block
//   blockIdx.x                  : j-chunk group
//   blockIdx.z                  : batch b
// Each thread copies U_J consecutive output rows at its column q.
// row(j) = ((j + shift_t) % P) % L, with P = 3*min(lengths).
// Given the bench's input contract (L > N/2), j+shift < P always, so the P-mod
// is a no-op on the fast path; a guarded slow path keeps full generality.
__global__ __launch_bounds__(240, 8) void rc_gather_kernel(
    const float4* __restrict__ x,       // (B, N, 60) float4
    const int*    __restrict__ lengths, // (B,)
    float4*       __restrict__ out,     // (B, max_len, 60) float4
    int N, int max_len)
{
    const int q = threadIdx.x;                                  // 0..59
    const int b = blockIdx.z;
    const int jgrp = blockIdx.x * blockDim.y + threadIdx.y;
    const int j0 = jgrp * U_J;
    if (j0 >= max_len) return;

    const int L = __ldg(lengths + b);
    const int P = 3 * g_minlen;

    const int t = q >> 2;                      // track id 0..14
    const int shift = (1u << t) >> 1;          // 0,1,2,4,...,2^13

    int v0 = j0 + shift;
    while (v0 >= P) v0 -= P;                   // at most 1 iter in practice (0 here)
    int row0 = v0;
    while (row0 >= L) row0 -= L;               // v0 < 3L -> <=2 iters

    const float4* __restrict__ src_base = x + (size_t)b * N * ROW_F4 + q;
    float4* __restrict__ dst = out + ((size_t)b * max_len + j0) * ROW_F4 + q;

    const int rem = max_len - j0;

    if (rem >= U_J && v0 + U_J <= P && L > U_J) {
        // Fast path: rows are row0+u with at most one -L wrap; all iterations
        // independent -> full MLP, stores coalesced across q lanes.
        #pragma unroll
        for (int u = 0; u < U_J; ++u) {
            int r = row0 + u;
            if (r >= L) r -= L;
            dst[(size_t)u * ROW_F4] = __ldg(src_base + (size_t)r * ROW_F4);
        }
    } else {
        // General / tail path.
        int v = v0, r = row0;
        const int n_it = rem < U_J ? rem : U_J;
        for (int u = 0; u < n_it; ++u) {
            dst[(size_t)u * ROW_F4] = __ldg(src_base + (size_t)r * ROW_F4);
            ++v; ++r;
            if (v >= P) { v = 0; r = 0; }
            else if (r >= L) r = 0;
        }
    }
}

extern "C" void kernel_launch(void* const* d_in, const int* in_sizes, int n_in,
                              void* d_out, int out_size) {
    const float* x       = (const float*)d_in[0];
    const int*   lengths = (const int*)d_in[1];
    float*       out     = (float*)d_out;

    const int B = in_sizes[1];                       // 8
    const int N = in_sizes[0] / (B * C_TOT);         // 16384
    const int max_len = out_size / (B * C_TOT);      // max(lengths)

    rc_min_kernel<<<1, 1>>>(lengths, B);

    const int jgrps = (max_len + U_J - 1) / U_J;     // 1024
    dim3 blk(ROW_F4, 4, 1);                          // 240 threads
    dim3 grid((jgrps + 3) / 4, 1, B);                // (256,1,8)
    rc_gather_kernel<<<grid, blk>>>((const float4*)x, lengths, (float4*)out,
                                    N, max_len);
}

// round 2
// speedup vs baseline: 1.1029x; 1.1029x over previous
#include <cuda_runtime.h>
#include <cuda_bf16.h>

// Problem constants (reference: TRACK_SIZE=16, C=240 -> T=15 tracks).
#define C_TOT      240
#define ROW_F4     60      // float4 per row (240 floats / 4)
#define U_J        16      // consecutive j-rows per thread
#define PH         8       // load/store phase depth (MLP per thread)

// Thread layout:
//   threadIdx.x = q in [0,60) : float4 column (stores coalesced across lanes)
//   threadIdx.y in [0,4)      : j-chunk subgroup
//   blockIdx.x                : j-chunk group, blockIdx.z = batch b
// row(j) = ((j + shift_t) % P) % L, P = 3*min(lengths).
__global__ __launch_bounds__(240, 4) void rc_gather_kernel(
    const float4* __restrict__ x,       // (B, N, 60) float4
    const int*    __restrict__ lengths, // (B,)
    float4*       __restrict__ out,     // (B, max_len, 60) float4
    int B, int N, int max_len)
{
    const int q = threadIdx.x;                                  // 0..59
    const int b = blockIdx.z;
    const int jgrp = blockIdx.x * blockDim.y + threadIdx.y;
    const int j0 = jgrp * U_J;
    if (j0 >= max_len) return;

    // min(lengths): B is tiny (8); these LDGs hit L1/L2 immediately.
    int minL = __ldg(lengths);
    #pragma unroll 4
    for (int i = 1; i < B; ++i) minL = min(minL, __ldg(lengths + i));
    const int P = 3 * minL;
    const int L = __ldg(lengths + b);

    const int t = q >> 2;                      // track id 0..14
    const int shift = (1u << t) >> 1;          // 0,1,2,4,...,2^13

    int v0 = j0 + shift;
    while (v0 >= P) v0 -= P;
    int row0 = v0;
    while (row0 >= L) row0 -= L;

    const float4* __restrict__ src = x + (size_t)b * N * ROW_F4 + q;
    float4* __restrict__ dst = out + ((size_t)b * max_len + j0) * ROW_F4 + q;

    const int rem = max_len - j0;

    if (rem >= U_J && v0 + U_J <= P && L > U_J) {
        // Fast path: two phases of PH=8 batched loads -> batched streaming
        // stores. The explicit v[] array forces ptxas to keep 8 loads in
        // flight per thread (MLP=8).
        #pragma unroll
        for (int ph = 0; ph < U_J / PH; ++ph) {
            float4 v[PH];
            #pragma unroll
            for (int u = 0; u < PH; ++u) {
                int r = row0 + ph * PH + u;
                if (r >= L) r -= L;
                v[u] = __ldg(src + (size_t)r * ROW_F4);
            }
            #pragma unroll
            for (int u = 0; u < PH; ++u)
                __stcs(dst + (size_t)(ph * PH + u) * ROW_F4, v[u]);
        }
    } else {
        // General / tail path.
        int vv = v0, r = row0;
        const int n_it = rem < U_J ? rem : U_J;
        for (int u = 0; u < n_it; ++u) {
            __stcs(dst + (size_t)u * ROW_F4, __ldg(src + (size_t)r * ROW_F4));
            ++vv; ++r;
            if (vv >= P) { vv = 0; r = 0; }
            else if (r >= L) r = 0;
        }
    }
}

extern "C" void kernel_launch(void* const* d_in, const int* in_sizes, int n_in,
                              void* d_out, int out_size) {
    const float* x       = (const float*)d_in[0];
    const int*   lengths = (const int*)d_in[1];
    float*       out     = (float*)d_out;

    const int B = in_sizes[1];                       // 8
    const int N = in_sizes[0] / (B * C_TOT);         // 16384
    const int max_len = out_size / (B * C_TOT);      // max(lengths)

    const int jgrps = (max_len + U_J - 1) / U_J;     // 1024
    dim3 blk(ROW_F4, 4, 1);                          // 240 threads
    dim3 grid((jgrps + 3) / 4, 1, B);                // (256,1,8)
    rc_gather_kernel<<<grid, blk>>>((const float4*)x, lengths, (float4*)out,
                                    B, N, max_len);
}

// round 3
// speedup vs baseline: 1.1114x; 1.0077x over previous
#include <cuda_runtime.h>
#include <cuda_bf16.h>
#include <cstdint>

// Problem constants (reference: TRACK_SIZE=16, C=240 -> 15 tracks).
#define C_TOT   240
#define ROW_F4  60          // float4 per row
#define TJ      32          // output rows per CTA tile
#define TY      8           // blockDim.y
#define KPT     (TJ / TY)   // rows per thread (4)

// Each CTA produces one contiguous output tile (TJ rows x 240 cols = 30720 B):
//   gather loads (LDG.128) -> smem (STS.128, conflict-free) -> single TMA
//   bulk store (cp.async.bulk smem->gmem, bypasses L1 store path entirely).
// row(j,t) = ((j + shift_t) % P) % L, P = 3*min(lengths), shift_t = 2^(t-1).
__global__ __launch_bounds__(480, 4) void rc_gather_tma_kernel(
    const float4* __restrict__ x,       // (B, N, 60) float4
    const int*    __restrict__ lengths, // (B,)
    float*        __restrict__ out,     // (B, max_len, 240) float
    int B, int N, int max_len)
{
    __shared__ __align__(16) float4 tile[TJ * ROW_F4];   // 30 KB

    const int q  = threadIdx.x;        // 0..59 : float4 column
    const int ty = threadIdx.y;        // 0..7
    const int b  = blockIdx.z;
    const int j0 = blockIdx.x * TJ;
    if (j0 >= max_len) return;

    // min(lengths): B tiny; L2/L1-resident scalar loads.
    int minL = __ldg(lengths);
    #pragma unroll 4
    for (int i = 1; i < B; ++i) minL = min(minL, __ldg(lengths + i));
    const int P = 3 * minL;
    const int L = __ldg(lengths + b);

    const int t     = q >> 2;              // track 0..14
    const int shift = (1u << t) >> 1;      // 0,1,2,4,...,2^13

    const float4* __restrict__ src = x + (size_t)b * N * ROW_F4 + q;
    const int nrows = min(TJ, max_len - j0);

    // Phase 1: gathered loads (4 independent LDG.128 in flight per thread).
    float4 v[KPT];
    #pragma unroll
    for (int k = 0; k < KPT; ++k) {
        const int jl = ty + TY * k;
        int vv = j0 + jl + shift;
        while (vv >= P) vv -= P;           // generic circular pad
        int r = vv;
        while (r >= L) r -= L;             // <=2 iters (vv < 3L)
        if (jl < nrows)
            v[k] = __ldg(src + (size_t)r * ROW_F4);
    }

    // Phase 2: stage into smem (contiguous per warp -> conflict-free STS.128).
    #pragma unroll
    for (int k = 0; k < KPT; ++k) {
        const int jl = ty + TY * k;
        if (jl < nrows)
            tile[jl * ROW_F4 + q] = v[k];
    }
    __syncthreads();

    // Phase 3: one bulk TMA store of the whole contiguous tile.
    if (threadIdx.x == 0 && threadIdx.y == 0) {
        asm volatile("fence.proxy.async.shared::cta;" ::: "memory");
        uint32_t saddr;
        asm("{ .reg .u64 tt; cvta.to.shared.u64 tt, %1; cvt.u32.u64 %0, tt; }"
            : "=r"(saddr) : "l"(tile));
        float* gdst = out + ((size_t)b * max_len + j0) * C_TOT;
        const int bytes = nrows * ROW_F4 * 16;   // multiple of 16
        asm volatile(
            "cp.async.bulk.global.shared::cta.bulk_group [%0], [%1], %2;"
            :: "l"(gdst), "r"(saddr), "r"(bytes) : "memory");
        asm volatile("cp.async.bulk.commit_group;" ::: "memory");
        asm volatile("cp.async.bulk.wait_group 0;" ::: "memory");
    }
}

extern "C" void kernel_launch(void* const* d_in, const int* in_sizes, int n_in,
                              void* d_out, int out_size) {
    const float* x       = (const float*)d_in[0];
    const int*   lengths = (const int*)d_in[1];
    float*       out     = (float*)d_out;

    const int B = in_sizes[1];                    // 8
    const int N = in_sizes[0] / (B * C_TOT);      // 16384
    const int max_len = out_size / (B * C_TOT);   // max(lengths)

    dim3 blk(ROW_F4, TY, 1);                      // 480 threads
    dim3 grid((max_len + TJ - 1) / TJ, 1, B);     // (512,1,8)
    rc_gather_tma_kernel<<<grid, blk>>>((const float4*)x, lengths, out,
                                        B, N, max_len);
}